// round 3
// baseline (speedup 1.0000x reference)
#include <cuda_runtime.h>
#include <math.h>

#define NBLK1 128
#define NTHR  256
#define NWARP (NTHR / 32)

struct Pair { float v; int i; };

__device__ Pair g_pos[NBLK1 * 8];
__device__ Pair g_neg[NBLK1 * 8];

__device__ __forceinline__ bool better(float v1, int i1, float v2, int i2) {
    // jax.lax.top_k order: larger value first, ties -> lower index
    return (v1 > v2) || (v1 == v2 && i1 < i2);
}

__device__ __forceinline__ void pinit(Pair* t) {
#pragma unroll
    for (int k = 0; k < 8; k++) { t[k].v = -INFINITY; t[k].i = 0x7fffffff; }
}

// t sorted descending; insert (v,i) keeping top-8. Fully unrolled, no dynamic
// indexing (stays in registers, predicated bubble pass).
__device__ __forceinline__ void insert8(Pair* t, float v, int i) {
    if (!better(v, i, t[7].v, t[7].i)) return;   // hot path: 1 compare
    t[7].v = v; t[7].i = i;
#pragma unroll
    for (int k = 7; k > 0; --k) {
        if (better(t[k].v, t[k].i, t[k - 1].v, t[k - 1].i)) {
            Pair tmp = t[k - 1]; t[k - 1] = t[k]; t[k] = tmp;
        }
    }
}

// Merge 32 lanes' sorted-descending top-8 lists -> warp top-8 (identical on
// all lanes, sorted descending). Register-only (unrolled select ladder).
__device__ __forceinline__ void warp_top8(const Pair* t, Pair* out) {
    int head = 0;
#pragma unroll
    for (int r = 0; r < 8; ++r) {
        float v = -INFINITY; int i = 0x7fffffff;
#pragma unroll
        for (int k = 0; k < 8; ++k) if (k == head) { v = t[k].v; i = t[k].i; }
        float bv = v; int bi = i;
#pragma unroll
        for (int off = 16; off > 0; off >>= 1) {
            float ov = __shfl_xor_sync(0xffffffffu, bv, off);
            int   oi = __shfl_xor_sync(0xffffffffu, bi, off);
            if (better(ov, oi, bv, bi)) { bv = ov; bi = oi; }
        }
        if (head < 8 && v == bv && i == bi) head++;  // winner pops
        out[r].v = bv; out[r].i = bi;
    }
}

// ---------------- kernel 1: per-block top8 / bottom8 candidates ----------------
__global__ void __launch_bounds__(NTHR)
topk_part(const float* __restrict__ A, const int* __restrict__ bag,
          int N, int C)
{
    __shared__ Pair s[2 * NWARP * 8];

    int col = C - 1;
    if (bag) {
        int raw = bag[0];
        if (raw >= 0 && raw < C) col = raw;   // clamp (also defuses bad encodings)
    }

    const int tid = threadIdx.x;
    const int lane = tid & 31, warp = tid >> 5;

    Pair tp[8], tn[8];
    pinit(tp); pinit(tn);

    const int stride = gridDim.x * blockDim.x;
    for (int i = blockIdx.x * blockDim.x + tid; i < N; i += stride) {
        float v = __ldg(A + (long long)i * C + col);
        insert8(tp,  v, i);
        insert8(tn, -v, i);
    }

    Pair wp[8], wn[8];
    warp_top8(tp, wp);
    warp_top8(tn, wn);
    if (lane < 8) {
        s[warp * 8 + lane] = wp[lane];
        s[NWARP * 8 + warp * 8 + lane] = wn[lane];
    }
    __syncthreads();

    if (warp == 0) {
        Pair t2[8]; pinit(t2);
        for (int j = lane; j < NWARP * 8; j += 32) insert8(t2, s[j].v, s[j].i);
        Pair f8[8]; warp_top8(t2, f8);
        if (lane < 8) g_pos[blockIdx.x * 8 + lane] = f8[lane];
    } else if (warp == 1) {
        Pair t2[8]; pinit(t2);
        for (int j = lane; j < NWARP * 8; j += 32)
            insert8(t2, s[NWARP * 8 + j].v, s[NWARP * 8 + j].i);
        Pair f8[8]; warp_top8(t2, f8);
        if (lane < 8) g_neg[blockIdx.x * 8 + lane] = f8[lane];
    }
}

// ---------------- kernel 2: final reduce + gather GEMM + softmax ----------------
__global__ void __launch_bounds__(NTHR)
finalize(const float* __restrict__ h, const float* __restrict__ W,
         const float* __restrict__ b, float* __restrict__ out,
         int N, int D, int C, int nCand, int out_size)
{
    __shared__ Pair s[2 * NWARP * 8];
    __shared__ int  idx16[16];

    const int tid = threadIdx.x;
    const int lane = tid & 31, warp = tid >> 5;

    // warps 0-3 reduce g_pos, warps 4-7 reduce g_neg (128 threads each side)
    {
        const Pair* src = (warp < 4) ? g_pos : g_neg;
        const int half_tid = (warp < 4) ? tid : tid - 128;
        Pair t[8]; pinit(t);
        for (int j = half_tid; j < nCand; j += 128) insert8(t, src[j].v, src[j].i);
        Pair w8[8]; warp_top8(t, w8);
        if (lane < 8) s[warp * 8 + lane] = w8[lane];
    }
    __syncthreads();
    if (warp == 0 || warp == 4) {
        const int o = (warp == 0) ? 0 : 32;
        Pair t2[8]; pinit(t2);
        for (int j = lane; j < 32; j += 32) insert8(t2, s[o + j].v, s[o + j].i);
        Pair f8[8]; warp_top8(t2, f8);
        if (lane < 8) idx16[((warp == 0) ? 0 : 8) + lane] = f8[lane].i;
    }
    __syncthreads();

    // labels: 8 ones then 8 zeros (guarded writes)
    if (tid < 16 && tid < out_size) out[tid] = (tid < 8) ? 1.0f : 0.0f;

    // tiny GEMM + softmax: one warp per output row (C==2 fast path)
    if (C == 2) {
        for (int row = warp; row < 16; row += NWARP) {
            int idx = idx16[row];
            if (idx < 0 || idx >= N) idx = 0;          // defensive clamp
            const float* hr = h + (long long)idx * D;
            float a0 = 0.f, a1 = 0.f;
            for (int d = lane; d < D; d += 32) {
                float x = __ldg(hr + d);
                a0 = fmaf(x, __ldg(W + 2 * d + 0), a0);
                a1 = fmaf(x, __ldg(W + 2 * d + 1), a1);
            }
#pragma unroll
            for (int off = 16; off > 0; off >>= 1) {
                a0 += __shfl_xor_sync(0xffffffffu, a0, off);
                a1 += __shfl_xor_sync(0xffffffffu, a1, off);
            }
            if (lane == 0) {
                float l0 = a0 + b[0], l1 = a1 + b[1];
                float m  = fmaxf(l0, l1);
                float e0 = expf(l0 - m), e1 = expf(l1 - m);
                float inv = 1.f / (e0 + e1);
                if (16 + 2 * row < out_size) out[16 + 2 * row] = e0 * inv;
                if (17 + 2 * row < out_size) out[17 + 2 * row] = e1 * inv;
            }
        }
    } else {
        // generic fallback: warp computes each (row, c) sequentially
        for (int row = warp; row < 16; row += NWARP) {
            int idx = idx16[row];
            if (idx < 0 || idx >= N) idx = 0;
            const float* hr = h + (long long)idx * D;
            float m = -INFINITY, sum = 0.f;
            // first pass: logits -> shared via lane0 recompute (C small)
            for (int c = 0; c < C; ++c) {
                float a = 0.f;
                for (int d = lane; d < D; d += 32)
                    a = fmaf(__ldg(hr + d), __ldg(W + (long long)d * C + c), a);
#pragma unroll
                for (int off = 16; off > 0; off >>= 1)
                    a += __shfl_xor_sync(0xffffffffu, a, off);
                a += b[c];
                m = fmaxf(m, a);
            }
            for (int c = 0; c < C; ++c) {
                float a = 0.f;
                for (int d = lane; d < D; d += 32)
                    a = fmaf(__ldg(hr + d), __ldg(W + (long long)d * C + c), a);
#pragma unroll
                for (int off = 16; off > 0; off >>= 1)
                    a += __shfl_xor_sync(0xffffffffu, a, off);
                a += b[c];
                sum += expf(a - m);
            }
            for (int c = 0; c < C; ++c) {
                float a = 0.f;
                for (int d = lane; d < D; d += 32)
                    a = fmaf(__ldg(hr + d), __ldg(W + (long long)d * C + c), a);
#pragma unroll
                for (int off = 16; off > 0; off >>= 1)
                    a += __shfl_xor_sync(0xffffffffu, a, off);
                a += b[c];
                int o = 16 + row * C + c;
                if (lane == 0 && o < out_size) out[o] = expf(a - m) / sum;
            }
        }
    }
}

extern "C" void kernel_launch(void* const* d_in, const int* in_sizes, int n_in,
                              void* d_out, int out_size)
{
    // Identify inputs by element count (robust to ordering / missing scalar):
    //   h: N*D (largest), A: N*C (2nd), W: D*C, b: C, bag: 1 (optional)
    int ih = -1, ia = -1, iw = -1, ib = -1, ibag = -1;
    long long best1 = -1, best2 = -1;
    for (int k = 0; k < n_in; k++) {
        long long sz = in_sizes[k];
        if (sz > best1) { best2 = best1; ia = ih; best1 = sz; ih = k; }
        else if (sz > best2) { best2 = sz; ia = k; }
    }
    long long wbest = -1, bbest = -1;
    for (int k = 0; k < n_in; k++) {
        if (k == ih || k == ia) continue;
        long long sz = in_sizes[k];
        if (sz == 1 && ibag < 0) { ibag = k; continue; }
        if (sz > wbest) { bbest = wbest; ib = iw; wbest = sz; iw = k; }
        else if (sz > bbest) { bbest = sz; ib = k; }
    }

    const float* h   = (const float*)d_in[ih];
    const float* A   = (const float*)d_in[ia];
    const float* W   = (const float*)d_in[iw];
    const float* b   = (const float*)d_in[ib];
    const int*   bag = (ibag >= 0) ? (const int*)d_in[ibag] : nullptr;

    int C = in_sizes[ib];                           // b: (C,)
    int D = in_sizes[iw] / C;                       // W: (D, C)
    int N = (int)((long long)in_sizes[ih] / D);     // h: (N, D)

    topk_part<<<NBLK1, NTHR>>>(A, bag, N, C);
    finalize<<<1, NTHR>>>(h, W, b, (float*)d_out, N, D, C, NBLK1 * 8, out_size);
}

// round 4
// speedup vs baseline: 1.3384x; 1.3384x over previous
#include <cuda_runtime.h>
#include <math.h>

#define NBLK1 256
#define NTHR1 256
#define NW1   (NTHR1 / 32)
#define NTHR2 512
#define NW2   (NTHR2 / 32)
#define NCAND (NBLK1 * 8)

struct Pair { float v; int i; };

__device__ Pair g_pos[NCAND];
__device__ Pair g_neg[NCAND];

__device__ __forceinline__ bool better(float v1, int i1, float v2, int i2) {
    // jax.lax.top_k order: larger value first, ties -> lower index
    return (v1 > v2) || (v1 == v2 && i1 < i2);
}

__device__ __forceinline__ void pinit(Pair* t) {
#pragma unroll
    for (int k = 0; k < 8; k++) { t[k].v = -INFINITY; t[k].i = 0x7fffffff; }
}

// t sorted descending; insert (v,i) keeping top-8. Register-resident.
__device__ __forceinline__ void insert8(Pair* t, float v, int i) {
    if (!better(v, i, t[7].v, t[7].i)) return;   // hot path: 1 compare
    t[7].v = v; t[7].i = i;
#pragma unroll
    for (int k = 7; k > 0; --k) {
        if (better(t[k].v, t[k].i, t[k - 1].v, t[k - 1].i)) {
            Pair tmp = t[k - 1]; t[k - 1] = t[k]; t[k] = tmp;
        }
    }
}

// Merge 32 lanes' sorted-descending top-8 lists -> warp top-8 (identical on
// all lanes, sorted descending).
__device__ __forceinline__ void warp_top8(const Pair* t, Pair* out) {
    int head = 0;
#pragma unroll
    for (int r = 0; r < 8; ++r) {
        float v = -INFINITY; int i = 0x7fffffff;
#pragma unroll
        for (int k = 0; k < 8; ++k) if (k == head) { v = t[k].v; i = t[k].i; }
        float bv = v; int bi = i;
#pragma unroll
        for (int off = 16; off > 0; off >>= 1) {
            float ov = __shfl_xor_sync(0xffffffffu, bv, off);
            int   oi = __shfl_xor_sync(0xffffffffu, bi, off);
            if (better(ov, oi, bv, bi)) { bv = ov; bi = oi; }
        }
        if (head < 8 && v == bv && i == bi) head++;  // winner pops
        out[r].v = bv; out[r].i = bi;
    }
}

// ---------------- kernel 1: per-block top8 / bottom8 candidates ----------------
__global__ void __launch_bounds__(NTHR1)
topk_part(const float* __restrict__ A, const int* __restrict__ bag,
          int N, int C)
{
    __shared__ Pair s[2 * NW1 * 8];

    int col = C - 1;
    if (bag) { int raw = bag[0]; if (raw >= 0 && raw < C) col = raw; }

    const int tid = threadIdx.x;
    const int lane = tid & 31, warp = tid >> 5;

    Pair tp[8], tn[8];
    pinit(tp); pinit(tn);

    const int stride = gridDim.x * blockDim.x;       // in float4 units below
    if (C == 2 && ((N & 1) == 0)) {
        // float4 = A rows {2j, 2j+1}. Front-batch 4 independent loads (MLP=4).
        const float4* A4 = (const float4*)A;
        const int M = N >> 1;                        // number of float4s
        for (int j = blockIdx.x * blockDim.x + tid; j < M; j += 4 * stride) {
            float4 x0, x1, x2, x3;
            int j1 = j + stride, j2 = j + 2 * stride, j3 = j + 3 * stride;
            bool p1 = j1 < M, p2 = j2 < M, p3 = j3 < M;
            x0 = A4[j];
            x1 = p1 ? A4[j1] : make_float4(0.f, 0.f, 0.f, 0.f);
            x2 = p2 ? A4[j2] : make_float4(0.f, 0.f, 0.f, 0.f);
            x3 = p3 ? A4[j3] : make_float4(0.f, 0.f, 0.f, 0.f);

            float v0 = col ? x0.y : x0.x, v1 = col ? x0.w : x0.z;
            insert8(tp,  v0, 2 * j);     insert8(tn, -v0, 2 * j);
            insert8(tp,  v1, 2 * j + 1); insert8(tn, -v1, 2 * j + 1);
            if (p1) {
                float a = col ? x1.y : x1.x, c = col ? x1.w : x1.z;
                insert8(tp,  a, 2 * j1);     insert8(tn, -a, 2 * j1);
                insert8(tp,  c, 2 * j1 + 1); insert8(tn, -c, 2 * j1 + 1);
            }
            if (p2) {
                float a = col ? x2.y : x2.x, c = col ? x2.w : x2.z;
                insert8(tp,  a, 2 * j2);     insert8(tn, -a, 2 * j2);
                insert8(tp,  c, 2 * j2 + 1); insert8(tn, -c, 2 * j2 + 1);
            }
            if (p3) {
                float a = col ? x3.y : x3.x, c = col ? x3.w : x3.z;
                insert8(tp,  a, 2 * j3);     insert8(tn, -a, 2 * j3);
                insert8(tp,  c, 2 * j3 + 1); insert8(tn, -c, 2 * j3 + 1);
            }
        }
    } else {
        for (int i = blockIdx.x * blockDim.x + tid; i < N; i += stride) {
            float v = __ldg(A + (long long)i * C + col);
            insert8(tp,  v, i);
            insert8(tn, -v, i);
        }
    }

    Pair wp[8], wn[8];
    warp_top8(tp, wp);
    warp_top8(tn, wn);
    if (lane < 8) {
        s[warp * 8 + lane] = wp[lane];
        s[NW1 * 8 + warp * 8 + lane] = wn[lane];
    }
    __syncthreads();

    if (warp == 0) {
        Pair t2[8]; pinit(t2);
        for (int j = lane; j < NW1 * 8; j += 32) insert8(t2, s[j].v, s[j].i);
        Pair f8[8]; warp_top8(t2, f8);
        if (lane < 8) g_pos[blockIdx.x * 8 + lane] = f8[lane];
    } else if (warp == 1) {
        Pair t2[8]; pinit(t2);
        for (int j = lane; j < NW1 * 8; j += 32)
            insert8(t2, s[NW1 * 8 + j].v, s[NW1 * 8 + j].i);
        Pair f8[8]; warp_top8(t2, f8);
        if (lane < 8) g_neg[blockIdx.x * 8 + lane] = f8[lane];
    }
}

// ---------------- kernel 2: final reduce + gather GEMM + softmax ----------------
__global__ void __launch_bounds__(NTHR2)
finalize(const float* __restrict__ h, const float* __restrict__ W,
         const float* __restrict__ b, float* __restrict__ out,
         int N, int D, int C, int out_size)
{
    __shared__ Pair s[2 * 8 * 8];       // 8 warps per side * 8 entries
    __shared__ int  idx16[16];

    const int tid = threadIdx.x;
    const int lane = tid & 31, warp = tid >> 5;

    // warps 0-7 reduce g_pos, warps 8-15 reduce g_neg (256 threads per side).
    // Vector loads: float4 = 2 Pairs; batch all iterations (independent LDGs).
    {
        const float4* src = (const float4*)((warp < 8) ? g_pos : g_neg);
        const int ht = (warp < 8) ? tid : tid - 256;  // 0..255
        const int npair4 = NCAND / 2;                 // 1024
        Pair t[8]; pinit(t);
#pragma unroll 4
        for (int j = ht; j < npair4; j += 256) {
            float4 f = src[j];
            insert8(t, f.x, __float_as_int(f.y));
            insert8(t, f.z, __float_as_int(f.w));
        }
        Pair w8[8]; warp_top8(t, w8);
        if (lane < 8) s[warp * 8 + lane] = w8[lane];
    }
    __syncthreads();
    if (warp == 0 || warp == 8) {
        const int o = (warp == 0) ? 0 : 64;
        Pair t2[8]; pinit(t2);
#pragma unroll 2
        for (int j = lane; j < 64; j += 32) insert8(t2, s[o + j].v, s[o + j].i);
        Pair f8[8]; warp_top8(t2, f8);
        if (lane < 8) idx16[((warp == 0) ? 0 : 8) + lane] = f8[lane].i;
    }
    __syncthreads();

    if (tid < 16 && tid < out_size) out[tid] = (tid < 8) ? 1.0f : 0.0f;

    if (C == 2 && (D & 3) == 0) {
        // one warp per output row; 4 independent float4 h-loads per lane
        if (warp < 16) {
            int idx = idx16[warp];
            if (idx < 0 || idx >= N) idx = 0;
            const float4* h4 = (const float4*)(h + (long long)idx * D);
            const float4* W4 = (const float4*)W;
            const int D4 = D >> 2;
            float a0 = 0.f, a1 = 0.f;
#pragma unroll 4
            for (int k = lane; k < D4; k += 32) {
                float4 x  = h4[k];
                float4 w0 = W4[2 * k];
                float4 w1 = W4[2 * k + 1];
                a0 = fmaf(x.x, w0.x, fmaf(x.y, w0.z, fmaf(x.z, w1.x, fmaf(x.w, w1.z, a0))));
                a1 = fmaf(x.x, w0.y, fmaf(x.y, w0.w, fmaf(x.z, w1.y, fmaf(x.w, w1.w, a1))));
            }
#pragma unroll
            for (int off = 16; off > 0; off >>= 1) {
                a0 += __shfl_xor_sync(0xffffffffu, a0, off);
                a1 += __shfl_xor_sync(0xffffffffu, a1, off);
            }
            if (lane == 0) {
                float l0 = a0 + b[0], l1 = a1 + b[1];
                float m  = fmaxf(l0, l1);
                float e0 = __expf(l0 - m), e1 = __expf(l1 - m);
                float inv = 1.f / (e0 + e1);
                if (16 + 2 * warp < out_size) out[16 + 2 * warp] = e0 * inv;
                if (17 + 2 * warp < out_size) out[17 + 2 * warp] = e1 * inv;
            }
        }
    } else {
        // generic scalar fallback
        for (int row = warp; row < 16; row += NW2) {
            int idx = idx16[row];
            if (idx < 0 || idx >= N) idx = 0;
            const float* hr = h + (long long)idx * D;
            float m = -INFINITY, sum = 0.f;
            for (int c = 0; c < C; ++c) {
                float a = 0.f;
                for (int d = lane; d < D; d += 32)
                    a = fmaf(__ldg(hr + d), __ldg(W + (long long)d * C + c), a);
#pragma unroll
                for (int off = 16; off > 0; off >>= 1)
                    a += __shfl_xor_sync(0xffffffffu, a, off);
                a += b[c];
                m = fmaxf(m, a);
            }
            for (int c = 0; c < C; ++c) {
                float a = 0.f;
                for (int d = lane; d < D; d += 32)
                    a = fmaf(__ldg(hr + d), __ldg(W + (long long)d * C + c), a);
#pragma unroll
                for (int off = 16; off > 0; off >>= 1)
                    a += __shfl_xor_sync(0xffffffffu, a, off);
                a += b[c];
                sum += __expf(a - m);
            }
            for (int c = 0; c < C; ++c) {
                float a = 0.f;
                for (int d = lane; d < D; d += 32)
                    a = fmaf(__ldg(hr + d), __ldg(W + (long long)d * C + c), a);
#pragma unroll
                for (int off = 16; off > 0; off >>= 1)
                    a += __shfl_xor_sync(0xffffffffu, a, off);
                a += b[c];
                int o = 16 + row * C + c;
                if (lane == 0 && o < out_size) out[o] = __expf(a - m) / sum;
            }
        }
    }
}

extern "C" void kernel_launch(void* const* d_in, const int* in_sizes, int n_in,
                              void* d_out, int out_size)
{
    // Identify inputs by element count:
    //   h: N*D (largest), A: N*C (2nd), W: D*C, b: C, bag: 1 (optional)
    int ih = -1, ia = -1, iw = -1, ib = -1, ibag = -1;
    long long best1 = -1, best2 = -1;
    for (int k = 0; k < n_in; k++) {
        long long sz = in_sizes[k];
        if (sz > best1) { best2 = best1; ia = ih; best1 = sz; ih = k; }
        else if (sz > best2) { best2 = sz; ia = k; }
    }
    long long wbest = -1, bbest = -1;
    for (int k = 0; k < n_in; k++) {
        if (k == ih || k == ia) continue;
        long long sz = in_sizes[k];
        if (sz == 1 && ibag < 0) { ibag = k; continue; }
        if (sz > wbest) { bbest = wbest; ib = iw; wbest = sz; iw = k; }
        else if (sz > bbest) { bbest = sz; ib = k; }
    }

    const float* h   = (const float*)d_in[ih];
    const float* A   = (const float*)d_in[ia];
    const float* W   = (const float*)d_in[iw];
    const float* b   = (const float*)d_in[ib];
    const int*   bag = (ibag >= 0) ? (const int*)d_in[ibag] : nullptr;

    int C = in_sizes[ib];
    int D = in_sizes[iw] / C;
    int N = (int)((long long)in_sizes[ih] / D);

    topk_part<<<NBLK1, NTHR1>>>(A, bag, N, C);
    finalize<<<1, NTHR2>>>(h, W, b, (float*)d_out, N, D, C, out_size);
}